// round 7
// baseline (speedup 1.0000x reference)
#include <cuda_runtime.h>
#include <cuda_fp16.h>
#include <math.h>

#define NSAMP 32768
#define NFRM  127
#define MPAD  128
#define NB    4
#define WIN   512
#define STEP  256
#define DTRUNC 256
#define PADT  512
#define LPAD  (PADT + NSAMP)

#define NT    256           // lag-tile width per block
#define KC    128           // K chunk staged in SMEM
#define CSTR  792           // shifted-copy stride (elements)
#define CLEN  776           // shifted-copy length (elements)
#define MTILES (NSAMP/NT)   // 128

__device__ float g_frames[NB*NFRM*WIN];
__device__ __half g_ah[NB*MPAD*WIN];
__device__ __half g_th[NB*LPAD + 16];
__device__ unsigned long long g_tkey[NB*NFRM*MTILES];
__device__ float g_Y[NB*NSAMP];
__device__ double g_sum;

// ---------------- helpers ----------------
__device__ __forceinline__ unsigned smem_u32(const void* p) {
    unsigned a;
    asm("{ .reg .u64 t; cvta.to.shared.u64 t, %1; cvt.u32.u64 %0, t; }" : "=r"(a) : "l"(p));
    return a;
}
__device__ __forceinline__ unsigned encf(float v) {
    unsigned b = __float_as_uint(v);
    return (b & 0x80000000u) ? ~b : (b | 0x80000000u);
}
__device__ __forceinline__ float decf(unsigned e) {
    return (e & 0x80000000u) ? __uint_as_float(e ^ 0x80000000u) : __uint_as_float(~e);
}

#define LDSM_X4(r, addr) \
    asm volatile("ldmatrix.sync.aligned.m8n8.x4.shared.b16 {%0,%1,%2,%3}, [%4];" \
        : "=r"((r)[0]), "=r"((r)[1]), "=r"((r)[2]), "=r"((r)[3]) : "r"(addr))
#define LDSM_X4T(r, addr) \
    asm volatile("ldmatrix.sync.aligned.m8n8.x4.trans.shared.b16 {%0,%1,%2,%3}, [%4];" \
        : "=r"((r)[0]), "=r"((r)[1]), "=r"((r)[2]), "=r"((r)[3]) : "r"(addr))
#define MMA16816H(d, a, b0, b1) \
    asm volatile("mma.sync.aligned.m16n8k16.row.col.f16.f16.f16.f16 " \
        "{%0,%1}, {%2,%3,%4,%5}, {%6,%7}, {%0,%1};" \
        : "+r"((d)[0]), "+r"((d)[1]) \
        : "r"((a)[0]), "r"((a)[1]), "r"((a)[2]), "r"((a)[3]), "r"(b0), "r"(b1))

// ---------------------------------------------------------------------------
// prep: windowed frames (fp32 + fp16), padded fp16 target
// ---------------------------------------------------------------------------
__global__ void k_prep(const float* __restrict__ recon, const float* __restrict__ target) {
    int i = blockIdx.x * blockDim.x + threadIdx.x;
    if (i < NB*MPAD*WIN) {
        int t = i & (WIN-1);
        int f = (i >> 9) & (MPAD-1);
        int b = i >> 16;
        float v = 0.f;
        if (f < NFRM) {
            float wv = 0.54f - 0.46f * cospif((float)t * (1.0f/256.0f));
            v = wv * recon[b*NSAMP + f*STEP + t];
            g_frames[(b*NFRM + f)*WIN + t] = v;
        }
        g_ah[i] = __float2half(v);
    }
    if (i < NB*LPAD) {
        int b = i / LPAD, j = i - b*LPAD;
        float tv = (j >= PADT) ? target[b*NSAMP + j - PADT] : 0.f;
        g_th[i] = __float2half(tv);
    }
    if (i < 16) g_th[NB*LPAD + i] = __float2half(0.f);
    if (i < NB*NSAMP) g_Y[i] = 0.f;
    if (i == 0) g_sum = 0.0;
}

// ---------------------------------------------------------------------------
// Stage 1: fp16-accumulator mma.sync Toeplitz GEMM; per-(frame,tile) best key.
// D[f][n] = sum_k A[f][k] * t[m0+n-k].  128 frames x 256 lags per CTA.
// B never materialized: ldmatrix.trans reads 16B rows from 8 byte-shifted
// copies of the target slice (copy choice = alignment residue).
// ---------------------------------------------------------------------------
__global__ void __launch_bounds__(256) k_conv_mma() {
    __shared__ __align__(16) __half smA[MPAD*KC];     // swizzled A chunk (32 KB)
    __shared__ __align__(16) __half smT[8*CSTR];      // shifted target copies
    __shared__ unsigned long long red[MPAD];

    const int tid = threadIdx.x, lane = tid & 31, warp = tid >> 5;
    const int b = blockIdx.y, m0 = blockIdx.x * NT;
    const int wm = warp & 3, wn = warp >> 2;          // 4 M-warps x 2 N-warps
    const int mbase = wm*32, nbase = wn*128;
    const int idx = lane & 15, half = lane >> 4;
    const unsigned sA = smem_u32(smA), sT = smem_u32(smT);

    if (tid < MPAD) red[tid] = 0ull;

    unsigned acc[2][16][2];
    #pragma unroll
    for (int mi = 0; mi < 2; ++mi)
        #pragma unroll
        for (int nj = 0; nj < 16; ++nj)
            { acc[mi][nj][0] = 0u; acc[mi][nj][1] = 0u; }

    const int rowA0 = mbase + idx, rowA1 = mbase + 16 + idx;
    const unsigned aB0 = sA + rowA0*(KC*2), swz0 = (unsigned)(rowA0 & 7);
    const unsigned aB1 = sA + rowA1*(KC*2), swz1 = (unsigned)(rowA1 & 7);

    // B element e = 512 - krow + ncol; copy c8 makes the 16B row aligned
    const int c8 = (8 - (idx & 7)) & 7;
    const unsigned P = sT + (unsigned)(c8*(CSTR*2))
                     + (unsigned)((512 - idx + nbase + 8*half - c8) * 2);

    const __half* asrc = g_ah + b*MPAD*WIN;
    {   // shifted target copies (built once)
        const __half* tsrc = g_th + b*LPAD + m0;
        #pragma unroll
        for (int c = 0; c < 8; ++c)
            for (int i = tid; i < CLEN; i += 256)
                smT[c*CSTR + i] = tsrc[i + c];
    }

    for (int ch = 0; ch < 4; ++ch) {
        __syncthreads();                           // smT ready / prev mma done
        #pragma unroll
        for (int r = 0; r < 8; ++r) {              // stage A chunk (swizzled)
            int i = tid + 256*r;
            int m = i >> 4, u = i & 15;
            uint4 v = *(const uint4*)(asrc + m*WIN + ch*KC + u*8);
            *(uint4*)((char*)smA + m*(KC*2) + ((((unsigned)u) ^ (m & 7)) << 4)) = v;
        }
        __syncthreads();
        #pragma unroll
        for (int s = 0; s < 8; ++s) {
            const int S = ch*8 + s;                // k16-step
            unsigned a0[4], a1[4], bb[8][4];
            unsigned u = (unsigned)(2*s + half);
            LDSM_X4(a0, aB0 + ((u ^ swz0) << 4));
            LDSM_X4(a1, aB1 + ((u ^ swz1) << 4));
            unsigned baddr = P - 32u*(unsigned)S;
            #pragma unroll
            for (int j = 0; j < 8; ++j)
                LDSM_X4T(bb[j], baddr + 32u*(unsigned)j);
            #pragma unroll
            for (int j = 0; j < 8; ++j) {
                MMA16816H(acc[0][2*j],   a0, bb[j][0], bb[j][1]);
                MMA16816H(acc[0][2*j+1], a0, bb[j][2], bb[j][3]);
                MMA16816H(acc[1][2*j],   a1, bb[j][0], bb[j][1]);
                MMA16816H(acc[1][2*j+1], a1, bb[j][2], bb[j][3]);
            }
        }
    }

    // epilogue: per-row argmax keys -> quad shfl -> shared atomicMax -> tkey
    const int c0 = (lane & 3) * 2, r0 = lane >> 2;
    #pragma unroll
    for (int mi = 0; mi < 2; ++mi) {
        #pragma unroll
        for (int q = 0; q < 2; ++q) {
            unsigned long long best = 0ull;
            #pragma unroll
            for (int nj = 0; nj < 16; ++nj) {
                float2 vv = __half22float2(*(const __half2*)&acc[mi][nj][q]);
                unsigned m = (unsigned)(m0 + nbase + 8*nj + c0);
                unsigned long long k0 = ((unsigned long long)encf(vv.x) << 32)
                                      | (unsigned long long)(0xFFFFFFFFu - m);
                unsigned long long k1 = ((unsigned long long)encf(vv.y) << 32)
                                      | (unsigned long long)(0xFFFFFFFFu - (m+1));
                if (k0 > best) best = k0;
                if (k1 > best) best = k1;
            }
            unsigned long long o;
            o = __shfl_xor_sync(0xFFFFFFFFu, best, 1); if (o > best) best = o;
            o = __shfl_xor_sync(0xFFFFFFFFu, best, 2); if (o > best) best = o;
            if ((lane & 3) == 0)
                atomicMax(&red[mbase + 16*mi + 8*q + r0], best);
        }
    }
    __syncthreads();
    if (tid < NFRM)
        g_tkey[(b*NFRM + tid)*MTILES + blockIdx.x] = red[tid];
}

// ---------------------------------------------------------------------------
// Stage 2 + synth (fused, one block per (frame,batch)):
//  a) exact fp32 argmax refinement over tiles within margin of the approx max
//  b) positioned frame = frame (x) h placed at integer offset p:
//     d = 2p/65538;  h[m] = (-1)^m sin(pi d) cot(pi (m+d)/65536) / 65536
// ---------------------------------------------------------------------------
#define NOUT (WIN + 2*DTRUNC)       // 1024
#define R2   (NOUT/256)             // 4
#define HPAD 512
#define HLEN (HPAD + NOUT)          // h nonzero only on [HPAD, HPAD+2*DTRUNC]

__global__ void __launch_bounds__(256) k_synth(const float* __restrict__ target) {
    __shared__ float hp[HLEN];
    __shared__ float a_s[WIN];
    __shared__ unsigned long long skey[256];
    const int f = blockIdx.x, b = blockIdx.y;
    const int tid = threadIdx.x;

    for (int i = tid; i < WIN; i += 256) a_s[i] = g_frames[(b*NFRM + f)*WIN + i];

    // ---- stage A: approx max over tile keys, threshold ----
    const unsigned long long* tk = g_tkey + (b*NFRM + f)*MTILES;
    skey[tid] = (tid < MTILES) ? tk[tid] : 0ull;
    __syncthreads();
    for (int s = 128; s > 0; s >>= 1) {
        if (tid < s && skey[tid+s] > skey[tid]) skey[tid] = skey[tid+s];
        __syncthreads();
    }
    const float vmax = decf((unsigned)(skey[0] >> 32));
    const unsigned ethr = encf(vmax - 0.05f*fabsf(vmax) - 0.25f);
    __syncthreads();

    // ---- stage B: exact fp32 recompute of qualifying tiles (1 lag/thread) ----
    const float* tgt = target + b*NSAMP;
    unsigned long long best = 0ull;
    for (int mt = 0; mt < MTILES; ++mt) {
        if ((unsigned)(tk[mt] >> 32) < ethr) continue;
        const int m = mt*NT + tid;
        float s = 0.f;
        #pragma unroll 4
        for (int t = 0; t < WIN; ++t) {
            int x = m - t;
            if (x >= 0) s = fmaf(a_s[t], tgt[x], s);
        }
        unsigned long long key = ((unsigned long long)encf(s) << 32)
                               | (unsigned long long)(0xFFFFFFFFu - (unsigned)m);
        if (key > best) best = key;
    }
    skey[tid] = best;
    __syncthreads();
    for (int s = 128; s > 0; s >>= 1) {
        if (tid < s && skey[tid+s] > skey[tid]) skey[tid] = skey[tid+s];
        __syncthreads();
    }
    const int p = (int)(0xFFFFFFFFu - (unsigned)(skey[0] & 0xFFFFFFFFull));

    // ---- synth ----
    const float delta = (float)(2.0 * (double)p / 65538.0);
    const float sd = sinpif(delta);

    for (int i = tid; i < HLEN; i += 256) {
        int k = i - HPAD;
        float h = 0.f;
        if (k >= 0 && k <= 2*DTRUNC) {
            int m = k - DTRUNC;
            if (p == 0) {
                h = (m == 0) ? 1.f : 0.f;
            } else {
                float arg = ((float)m + delta) * (1.0f / 65536.0f);
                float v = sd * (cospif(arg) / sinpif(arg)) * (1.0f / 65536.0f);
                h = (m & 1) ? -v : v;
            }
        }
        hp[i] = h;
    }
    __syncthreads();

    const int xi0 = tid * R2;
    float acc[R2], w[R2];
    #pragma unroll
    for (int j = 0; j < R2; ++j) { acc[j] = 0.f; w[j] = hp[HPAD + xi0 + j]; }

    #pragma unroll 16
    for (int t = 0; t < WIN; ++t) {
        float av = a_s[t];
        #pragma unroll
        for (int j = R2-1; j >= 1; --j) {
            acc[j] = fmaf(av, w[j], acc[j]);
            w[j] = w[j-1];
        }
        acc[0] = fmaf(av, w[0], acc[0]);
        w[0] = hp[HPAD + xi0 - 1 - t];
    }

    #pragma unroll
    for (int j = 0; j < R2; ++j) {
        int x = p - DTRUNC + xi0 + j;
        if (x >= 0 && x < NSAMP)
            atomicAdd(&g_Y[b*NSAMP + x], acc[j]);
    }
}

// ---------------------------------------------------------------------------
// mse + finalize
// ---------------------------------------------------------------------------
__global__ void k_mse(const float* __restrict__ target) {
    __shared__ double red[256];
    const int tid = threadIdx.x;
    double s = 0.0;
    for (int i = blockIdx.x*256 + tid; i < NB*NSAMP; i += gridDim.x*256) {
        double d = (double)g_Y[i] - (double)target[i];
        s += d * d;
    }
    red[tid] = s;
    __syncthreads();
    for (int st = 128; st > 0; st >>= 1) {
        if (tid < st) red[tid] += red[tid + st];
        __syncthreads();
    }
    if (tid == 0) atomicAdd(&g_sum, red[0]);
}

__global__ void k_fin(float* __restrict__ out) {
    out[0] = (float)(g_sum / (double)(NB*NSAMP));
}

extern "C" void kernel_launch(void* const* d_in, const int* in_sizes, int n_in,
                              void* d_out, int out_size) {
    const float* recon  = (const float*)d_in[0];
    const float* target = (const float*)d_in[1];
    float* out = (float*)d_out;
    (void)in_sizes; (void)n_in; (void)out_size;

    k_prep<<<(NB*MPAD*WIN + 255)/256, 256>>>(recon, target);
    k_conv_mma<<<dim3(MTILES, NB), 256>>>();
    k_synth<<<dim3(NFRM, NB), 256>>>(target);
    k_mse<<<256, 256>>>(target);
    k_fin<<<1, 1>>>(out);
}

// round 8
// speedup vs baseline: 1.4885x; 1.4885x over previous
#include <cuda_runtime.h>
#include <cuda_fp16.h>
#include <math.h>

#define NSAMP 32768
#define NFRM  127
#define MPAD  128
#define NB    4
#define WIN   512
#define STEP  256
#define DTRUNC 256
#define PADT  512
#define LPAD  (PADT + NSAMP)

#define NT    128           // lag-tile width per block
#define KC    128           // K chunk staged in SMEM
#define NCPY  9             // shifted copies (1..8 used; conflict-free LDSM)
#define CSTR  664           // shifted-copy stride (elements); S/16=83 odd -> bijective banks
#define CLEN  648           // shifted-copy length (elements)
#define MTILES (NSAMP/NT)   // 256

#define ABUF  (MPAD*KC*2)                       // one A buffer, bytes (32 KB)
#define SMEM_DYN (2*ABUF + NCPY*CSTR*2 + MPAD*8)

__device__ __align__(16) float g_frames[NB*NFRM*WIN];
__device__ __align__(16) __half g_ah[NB*MPAD*WIN];
__device__ __align__(16) __half g_th[NB*LPAD + 1024];
__device__ unsigned long long g_tkey[NB*NFRM*MTILES];
__device__ float g_Y[NB*NSAMP];
__device__ double g_sum;

// ---------------- helpers ----------------
__device__ __forceinline__ unsigned smem_u32(const void* p) {
    unsigned a;
    asm("{ .reg .u64 t; cvta.to.shared.u64 t, %1; cvt.u32.u64 %0, t; }" : "=r"(a) : "l"(p));
    return a;
}
__device__ __forceinline__ unsigned encf(float v) {
    unsigned b = __float_as_uint(v);
    return (b & 0x80000000u) ? ~b : (b | 0x80000000u);
}
__device__ __forceinline__ float decf(unsigned e) {
    return (e & 0x80000000u) ? __uint_as_float(e ^ 0x80000000u) : __uint_as_float(~e);
}

#define LDSM_X4(r, addr) \
    asm volatile("ldmatrix.sync.aligned.m8n8.x4.shared.b16 {%0,%1,%2,%3}, [%4];" \
        : "=r"((r)[0]), "=r"((r)[1]), "=r"((r)[2]), "=r"((r)[3]) : "r"(addr))
#define LDSM_X4T(r, addr) \
    asm volatile("ldmatrix.sync.aligned.m8n8.x4.trans.shared.b16 {%0,%1,%2,%3}, [%4];" \
        : "=r"((r)[0]), "=r"((r)[1]), "=r"((r)[2]), "=r"((r)[3]) : "r"(addr))
#define MMA16816(d, a, b0, b1) \
    asm volatile("mma.sync.aligned.m16n8k16.row.col.f32.f16.f16.f32 " \
        "{%0,%1,%2,%3}, {%4,%5,%6,%7}, {%8,%9}, {%0,%1,%2,%3};" \
        : "+f"((d)[0]), "+f"((d)[1]), "+f"((d)[2]), "+f"((d)[3]) \
        : "r"((a)[0]), "r"((a)[1]), "r"((a)[2]), "r"((a)[3]), "r"(b0), "r"(b1))
#define CPASYNC16(dst, src) \
    asm volatile("cp.async.cg.shared.global [%0], [%1], 16;" :: "r"(dst), "l"(src))
#define CPCOMMIT() asm volatile("cp.async.commit_group;" ::: "memory")
#define CPWAIT0()  asm volatile("cp.async.wait_group 0;" ::: "memory")

// ---------------------------------------------------------------------------
// prep: windowed frames (fp32 + fp16), padded fp16 target
// ---------------------------------------------------------------------------
__global__ void k_prep(const float* __restrict__ recon, const float* __restrict__ target) {
    int i = blockIdx.x * blockDim.x + threadIdx.x;
    if (i < NB*MPAD*WIN) {
        int t = i & (WIN-1);
        int f = (i >> 9) & (MPAD-1);
        int b = i >> 16;
        float v = 0.f;
        if (f < NFRM) {
            float wv = 0.54f - 0.46f * cospif((float)t * (1.0f/256.0f));
            v = wv * recon[b*NSAMP + f*STEP + t];
            g_frames[(b*NFRM + f)*WIN + t] = v;
        }
        g_ah[i] = __float2half(v);
    }
    if (i < NB*LPAD) {
        int b = i / LPAD, j = i - b*LPAD;
        float tv = (j >= PADT) ? target[b*NSAMP + j - PADT] : 0.f;
        g_th[i] = __float2half(tv);
    }
    if (i < 1024) g_th[NB*LPAD + i] = __float2half(0.f);
    if (i < NB*NSAMP) g_Y[i] = 0.f;
    if (i == 0) g_sum = 0.0;
}

// ---------------------------------------------------------------------------
// Stage 1: fp16 mma.sync Toeplitz GEMM (fp32 acc); per-(frame,tile) best key.
// D[f][n] = sum_k A[f][k] * t[m0+n-k].
// cp.async double-buffered A staging; 9-copy conflict-free smT for ldmatrix.
// ---------------------------------------------------------------------------
__global__ void __launch_bounds__(256) k_conv_mma() {
    extern __shared__ __align__(16) char dyn[];
    __half* smA = (__half*)dyn;                                   // 2 x 32 KB
    __half* smT = (__half*)(dyn + 2*ABUF);                        // 9 copies
    unsigned long long* red = (unsigned long long*)(dyn + 2*ABUF + NCPY*CSTR*2);

    const int tid = threadIdx.x, lane = tid & 31, warp = tid >> 5;
    const int b = blockIdx.y, m0 = blockIdx.x * NT;
    const int wm = warp & 3, wn = warp >> 2;          // 4 M-warps x 2 N-warps
    const int mbase = wm*32, nbase = wn*64;
    const int idx = lane & 15, half = lane >> 4;
    const unsigned sA = smem_u32(smA), sT = smem_u32(smT);

    if (tid < MPAD) red[tid] = 0ull;

    float acc[2][8][4];
    #pragma unroll
    for (int mi = 0; mi < 2; ++mi)
        #pragma unroll
        for (int nj = 0; nj < 8; ++nj)
            #pragma unroll
            for (int e = 0; e < 4; ++e) acc[mi][nj][e] = 0.f;

    const int rowA0 = mbase + idx, rowA1 = mbase + 16 + idx;
    const unsigned swz0 = (unsigned)(rowA0 & 7), swz1 = (unsigned)(rowA1 & 7);

    // B element e = 512 - krow + ncol; copy c8p in [1,8] -> aligned + conflict-free
    const int c8p = 8 - (idx & 7);
    const unsigned P = sT + (unsigned)(c8p*(CSTR*2))
                     + (unsigned)((512 - idx + nbase + 8*half - c8p) * 2);

    const __half* asrc = g_ah + b*MPAD*WIN;

    // prologue: async-stage chunk 0 into buffer 0
    {
        #pragma unroll
        for (int r = 0; r < 8; ++r) {
            int i = tid + 256*r;
            int m = i >> 4, u = i & 15;
            CPASYNC16(sA + m*(KC*2) + ((((unsigned)u) ^ (m & 7)) << 4),
                      asrc + m*WIN + u*8);
        }
        CPCOMMIT();
    }
    {   // shifted target copies 1..8 (built once, overlaps chunk-0 cp.async)
        const __half* tsrc = g_th + b*LPAD + m0;
        #pragma unroll
        for (int c = 1; c < NCPY; ++c)
            for (int i = tid; i < CLEN; i += 256)
                smT[c*CSTR + i] = tsrc[i + c];
    }

    for (int ch = 0; ch < 4; ++ch) {
        const int cur = ch & 1;
        CPWAIT0();
        __syncthreads();      // copies visible to all; prev MMAs done with other buf
        if (ch < 3) {         // async-stage next chunk into the other buffer
            const __half* src = asrc + (ch+1)*KC;
            const unsigned dstb = sA + (cur ^ 1)*ABUF;
            #pragma unroll
            for (int r = 0; r < 8; ++r) {
                int i = tid + 256*r;
                int m = i >> 4, u = i & 15;
                CPASYNC16(dstb + m*(KC*2) + ((((unsigned)u) ^ (m & 7)) << 4),
                          src + m*WIN + u*8);
            }
            CPCOMMIT();
        }
        const unsigned aB0 = sA + cur*ABUF + rowA0*(KC*2);
        const unsigned aB1 = sA + cur*ABUF + rowA1*(KC*2);
        #pragma unroll
        for (int s = 0; s < 8; ++s) {
            const int S = ch*8 + s;                // k16-step
            unsigned a0[4], a1[4], bb[4][4];
            unsigned u = (unsigned)(2*s + half);
            LDSM_X4(a0, aB0 + ((u ^ swz0) << 4));
            LDSM_X4(a1, aB1 + ((u ^ swz1) << 4));
            unsigned baddr = P - 32u*(unsigned)S;
            LDSM_X4T(bb[0], baddr);
            LDSM_X4T(bb[1], baddr + 32u);
            LDSM_X4T(bb[2], baddr + 64u);
            LDSM_X4T(bb[3], baddr + 96u);
            #pragma unroll
            for (int j = 0; j < 4; ++j) {
                MMA16816(acc[0][2*j],   a0, bb[j][0], bb[j][1]);
                MMA16816(acc[0][2*j+1], a0, bb[j][2], bb[j][3]);
                MMA16816(acc[1][2*j],   a1, bb[j][0], bb[j][1]);
                MMA16816(acc[1][2*j+1], a1, bb[j][2], bb[j][3]);
            }
        }
    }

    // epilogue: per-row argmax keys -> quad shfl -> shared atomicMax -> tkey
    const int c0 = (lane & 3) * 2, r0 = lane >> 2;
    __syncthreads();
    #pragma unroll
    for (int mi = 0; mi < 2; ++mi) {
        #pragma unroll
        for (int q = 0; q < 2; ++q) {
            unsigned long long best = 0ull;
            #pragma unroll
            for (int nj = 0; nj < 8; ++nj) {
                #pragma unroll
                for (int e = 0; e < 2; ++e) {
                    float v = acc[mi][nj][q*2 + e];
                    unsigned m = (unsigned)(m0 + nbase + 8*nj + c0 + e);
                    unsigned long long key = ((unsigned long long)encf(v) << 32)
                                           | (unsigned long long)(0xFFFFFFFFu - m);
                    if (key > best) best = key;
                }
            }
            unsigned long long o;
            o = __shfl_xor_sync(0xFFFFFFFFu, best, 1); if (o > best) best = o;
            o = __shfl_xor_sync(0xFFFFFFFFu, best, 2); if (o > best) best = o;
            if ((lane & 3) == 0)
                atomicMax(&red[mbase + 16*mi + 8*q + r0], best);
        }
    }
    __syncthreads();
    if (tid < NFRM)
        g_tkey[(b*NFRM + tid)*MTILES + blockIdx.x] = red[tid];
}

// ---------------------------------------------------------------------------
// Stage 2 + synth (fused, one block per (frame,batch)):
//  a) exact fp32 argmax refinement over tiles within margin of the approx max
//  b) positioned frame = frame (x) h placed at integer offset p:
//     d = 2p/65538;  h[m] = (-1)^m sin(pi d) cot(pi (m+d)/65536) / 65536
// ---------------------------------------------------------------------------
#define NOUT (WIN + 2*DTRUNC)       // 1024
#define R2   (NOUT/256)             // 4
#define HPAD 512
#define HLEN (HPAD + NOUT)

__global__ void __launch_bounds__(256) k_synth(const float* __restrict__ target) {
    __shared__ float hp[HLEN];
    __shared__ float a_s[WIN];
    __shared__ unsigned long long skey[256];
    const int f = blockIdx.x, b = blockIdx.y;
    const int tid = threadIdx.x;

    for (int i = tid; i < WIN; i += 256) a_s[i] = g_frames[(b*NFRM + f)*WIN + i];

    // ---- stage A: approx max over tile keys, threshold ----
    const unsigned long long* tk = g_tkey + (b*NFRM + f)*MTILES;
    skey[tid] = tk[tid];
    __syncthreads();
    for (int s = 128; s > 0; s >>= 1) {
        if (tid < s && skey[tid+s] > skey[tid]) skey[tid] = skey[tid+s];
        __syncthreads();
    }
    const float vmax = decf((unsigned)(skey[0] >> 32));
    const unsigned ethr = encf(vmax - 0.05f*fabsf(vmax) - 1e-3f);
    __syncthreads();

    // ---- stage B: exact fp32 recompute of qualifying tiles ----
    const float* tgt = target + b*NSAMP;
    const int lag_off = tid >> 1, halfsel = tid & 1;
    unsigned long long best = 0ull;
    for (int mt = 0; mt < MTILES; ++mt) {
        if ((unsigned)(tk[mt] >> 32) < ethr) continue;
        const int m = mt*NT + lag_off;
        float s = 0.f;
        const int t0 = halfsel*256;
        #pragma unroll 4
        for (int t = t0; t < t0 + 256; ++t) {
            int x = m - t;
            if (x >= 0) s = fmaf(a_s[t], tgt[x], s);
        }
        float o = __shfl_xor_sync(0xFFFFFFFFu, s, 1);
        float v = s + o;
        unsigned long long key = ((unsigned long long)encf(v) << 32)
                               | (unsigned long long)(0xFFFFFFFFu - (unsigned)m);
        if (halfsel == 0 && key > best) best = key;
    }
    skey[tid] = best;
    __syncthreads();
    for (int s = 128; s > 0; s >>= 1) {
        if (tid < s && skey[tid+s] > skey[tid]) skey[tid] = skey[tid+s];
        __syncthreads();
    }
    const int p = (int)(0xFFFFFFFFu - (unsigned)(skey[0] & 0xFFFFFFFFull));

    // ---- synth ----
    const float delta = (float)(2.0 * (double)p / 65538.0);
    const float sd = sinpif(delta);

    for (int i = tid; i < HLEN; i += 256) {
        int k = i - HPAD;
        float h = 0.f;
        if (k >= 0 && k <= 2*DTRUNC) {
            int m = k - DTRUNC;
            if (p == 0) {
                h = (m == 0) ? 1.f : 0.f;
            } else {
                float arg = ((float)m + delta) * (1.0f / 65536.0f);
                float v = sd * (cospif(arg) / sinpif(arg)) * (1.0f / 65536.0f);
                h = (m & 1) ? -v : v;
            }
        }
        hp[i] = h;
    }
    __syncthreads();

    const int xi0 = tid * R2;
    float acc[R2], w[R2];
    #pragma unroll
    for (int j = 0; j < R2; ++j) { acc[j] = 0.f; w[j] = hp[HPAD + xi0 + j]; }

    #pragma unroll 16
    for (int t = 0; t < WIN; ++t) {
        float av = a_s[t];
        #pragma unroll
        for (int j = R2-1; j >= 1; --j) {
            acc[j] = fmaf(av, w[j], acc[j]);
            w[j] = w[j-1];
        }
        acc[0] = fmaf(av, w[0], acc[0]);
        w[0] = hp[HPAD + xi0 - 1 - t];
    }

    #pragma unroll
    for (int j = 0; j < R2; ++j) {
        int x = p - DTRUNC + xi0 + j;
        if (x >= 0 && x < NSAMP)
            atomicAdd(&g_Y[b*NSAMP + x], acc[j]);
    }
}

// ---------------------------------------------------------------------------
// mse + finalize
// ---------------------------------------------------------------------------
__global__ void k_mse(const float* __restrict__ target) {
    __shared__ double red[256];
    const int tid = threadIdx.x;
    double s = 0.0;
    for (int i = blockIdx.x*256 + tid; i < NB*NSAMP; i += gridDim.x*256) {
        double d = (double)g_Y[i] - (double)target[i];
        s += d * d;
    }
    red[tid] = s;
    __syncthreads();
    for (int st = 128; st > 0; st >>= 1) {
        if (tid < st) red[tid] += red[tid + st];
        __syncthreads();
    }
    if (tid == 0) atomicAdd(&g_sum, red[0]);
}

__global__ void k_fin(float* __restrict__ out) {
    out[0] = (float)(g_sum / (double)(NB*NSAMP));
}

extern "C" void kernel_launch(void* const* d_in, const int* in_sizes, int n_in,
                              void* d_out, int out_size) {
    const float* recon  = (const float*)d_in[0];
    const float* target = (const float*)d_in[1];
    float* out = (float*)d_out;
    (void)in_sizes; (void)n_in; (void)out_size;

    cudaFuncSetAttribute(k_conv_mma, cudaFuncAttributeMaxDynamicSharedMemorySize, SMEM_DYN);

    k_prep<<<(NB*MPAD*WIN + 255)/256, 256>>>(recon, target);
    k_conv_mma<<<dim3(MTILES, NB), 256, SMEM_DYN>>>();
    k_synth<<<dim3(NFRM, NB), 256>>>(target);
    k_mse<<<256, 256>>>(target);
    k_fin<<<1, 1>>>(out);
}